// round 8
// baseline (speedup 1.0000x reference)
#include <cuda_runtime.h>
#include <cstdint>

#define MAXN 100000
#define DD 64
#define GRID1 740   // 5 waves of 148 SMs for both GEMM kernels

// ---- scratch (no allocations allowed) ----
__device__ __align__(16) float  g_hbuf[(size_t)MAXN * DD];   // h = (1+eps)*x + scatter [N,64]
__device__ __align__(16) float  g_h1[(size_t)MAXN * 2 * DD]; // pre-BN hidden           [N,128]
__device__ float  g_psum[128 * GRID1];                       // BN partials, TRANSPOSED [ch][blk]
__device__ float  g_psq [128 * GRID1];
__device__ float  g_scale[2 * DD];
__device__ float  g_shift[2 * DD];
__device__ int    g_is64;                                    // 1 if edge buffers are int64

// ---------------------------------------------------------------------------
// K0: dtype probe. edge_feats values are tiny (0/1). Read 32 int64 words:
// if all in [0,7] -> data really is int64; else it was downcast to int32.
// ---------------------------------------------------------------------------
__global__ void k_probe(const long long* __restrict__ ef)
{
    int ok = 1;
#pragma unroll
    for (int i = 0; i < 32; i++) {
        long long v = ef[i];
        if (v < 0 || v > 7) ok = 0;
    }
    g_is64 = ok;
}

// ---------------------------------------------------------------------------
// K1: h = (1+eps)*node_feats
// ---------------------------------------------------------------------------
__global__ void k_init(const float* __restrict__ nf, const float* __restrict__ eps, int n4)
{
    int i = blockIdx.x * blockDim.x + threadIdx.x;
    if (i < n4) {
        float s = 1.0f + eps[0];
        float4 v = ((const float4*)nf)[i];
        v.x *= s; v.y *= s; v.z *= s; v.w *= s;
        ((float4*)g_hbuf)[i] = v;
    }
}

// ---------------------------------------------------------------------------
// K2: edge messages + scatter-add.  2 edges per warp, 16 lanes x float4 each.
// ---------------------------------------------------------------------------
__global__ void k_edge(const float4* __restrict__ nf4,
                       const void* __restrict__ ef,    // [E,3]
                       const void* __restrict__ ei,    // [2,E]: row0=dst, row1=src
                       const float4* __restrict__ e0,
                       const float4* __restrict__ e1,
                       const float4* __restrict__ e2,
                       long long E, int Nn)
{
    int lane = threadIdx.x & 31;
    long long warpId = (long long)blockIdx.x * (blockDim.x >> 5) + (threadIdx.x >> 5);
    int half = lane >> 4;
    int q    = lane & 15;
    long long e = warpId * 2 + half;

    int src = 0, dst = 0, f0 = 0, f1 = 0, f2 = 0;
    if (q == 0 && e < E) {
        if (g_is64) {
            const long long* ei64 = (const long long*)ei;
            const long long* ef64 = (const long long*)ef + e * 3;
            dst = (int)ei64[e];
            src = (int)ei64[E + e];
            f0 = (int)ef64[0]; f1 = (int)ef64[1]; f2 = (int)ef64[2];
        } else {
            const int* ei32 = (const int*)ei;
            const int* ef32 = (const int*)ef + e * 3;
            dst = ei32[e];
            src = ei32[E + e];
            f0 = ef32[0]; f1 = ef32[1]; f2 = ef32[2];
        }
    }
    int leader = half << 4;
    dst = __shfl_sync(0xffffffffu, dst, leader);
    src = __shfl_sync(0xffffffffu, src, leader);
    f0  = __shfl_sync(0xffffffffu, f0,  leader);
    f1  = __shfl_sync(0xffffffffu, f1,  leader);
    f2  = __shfl_sync(0xffffffffu, f2,  leader);
    if (e >= E) return;
    if ((unsigned)src >= (unsigned)Nn || (unsigned)dst >= (unsigned)Nn) return;
    if ((unsigned)f0 > 4u || (unsigned)f1 > 5u || (unsigned)f2 > 1u) return;

    float4 a = e0[f0 * 16 + q];
    float4 b = e1[f1 * 16 + q];
    float4 c = e2[f2 * 16 + q];
    float4 n = nf4[(long long)src * 16 + q];

    float x = fmaxf(n.x + a.x + b.x + c.x, 0.0f);
    float y = fmaxf(n.y + a.y + b.y + c.y, 0.0f);
    float z = fmaxf(n.z + a.z + b.z + c.z, 0.0f);
    float w = fmaxf(n.w + a.w + b.w + c.w, 0.0f);

    float* p = g_hbuf + (long long)dst * 64 + q * 4;
    asm volatile("red.global.add.v4.f32 [%0], {%1,%2,%3,%4};"
                 :: "l"(p), "f"(x), "f"(y), "f"(z), "f"(w) : "memory");
}

// ---------------------------------------------------------------------------
// K3: h1 = h @ W1^T + b1 + BN partial stats.
// W row in registers; broadcast-LDS inner loop; double-buffered staging with
// prefetch; one sync/iter. Partials stored TRANSPOSED for coalesced k_bn.
// ---------------------------------------------------------------------------
__global__ void __launch_bounds__(128, 5) k_gemm1(const float* __restrict__ W1,  // [128,64]
                                                  const float* __restrict__ b1,
                                                  int N)
{
    __shared__ float4 hsh[2][8 * 16];  // double buffer: 8 rows x 64 floats
    int tid = threadIdx.x;
    int rowoff = tid >> 4;     // 0..7
    int kslot  = tid & 15;     // float4 slot

    float4 w[16];
#pragma unroll
    for (int k4 = 0; k4 < 16; k4++)
        w[k4] = ((const float4*)W1)[tid * 16 + k4];
    float bj = __ldg(b1 + tid);

    float lsum = 0.0f, lsq = 0.0f;

    long long step = (long long)GRID1 * 8;
    long long r0 = (long long)blockIdx.x * 8;

    // prefetch tile 0
    float4 v = make_float4(0.f, 0.f, 0.f, 0.f);
    if (r0 + rowoff < N) v = ((const float4*)g_hbuf)[(r0 + rowoff) * 16 + kslot];

    int buf = 0;
    for (; r0 < N; r0 += step) {
        hsh[buf][tid] = v;
        __syncthreads();

        // prefetch next tile (overlaps with compute below)
        long long rn = r0 + step;
        if (rn + rowoff < N) v = ((const float4*)g_hbuf)[(rn + rowoff) * 16 + kslot];
        else                 v = make_float4(0.f, 0.f, 0.f, 0.f);

        float acc[8];
#pragma unroll
        for (int r = 0; r < 8; r++) acc[r] = bj;
#pragma unroll
        for (int k4 = 0; k4 < 16; k4++) {
            float4 wv = w[k4];
#pragma unroll
            for (int r = 0; r < 8; r++) {
                float4 h = hsh[buf][r * 16 + k4];
                acc[r] += wv.x * h.x + wv.y * h.y + wv.z * h.z + wv.w * h.w;
            }
        }

        long long base = r0 * 128 + tid;
#pragma unroll
        for (int r = 0; r < 8; r++) {
            if (r0 + r < N) {
                float a = acc[r];
                g_h1[base + r * 128] = a;
                lsum += a; lsq += a * a;
            }
        }
        buf ^= 1;
    }
    g_psum[tid * GRID1 + blockIdx.x] = lsum;   // transposed: [channel][block]
    g_psq [tid * GRID1 + blockIdx.x] = lsq;
}

// ---------------------------------------------------------------------------
// K4 v3: 128 blocks (one per channel) x 256 threads; coalesced per-channel
// reduction of GRID1 partials, double accumulation, fold into scale/shift.
// ---------------------------------------------------------------------------
__global__ void __launch_bounds__(256) k_bn(const float* __restrict__ gamma,
                                            const float* __restrict__ beta,
                                            double invN)
{
    __shared__ double ss[256], qq[256];
    int j = blockIdx.x;
    int t = threadIdx.x;

    double s = 0.0, q = 0.0;
    for (int b = t; b < GRID1; b += 256) {
        s += (double)g_psum[j * GRID1 + b];
        q += (double)g_psq [j * GRID1 + b];
    }
    ss[t] = s; qq[t] = q;
    __syncthreads();
    for (int off = 128; off > 0; off >>= 1) {
        if (t < off) { ss[t] += ss[t + off]; qq[t] += qq[t + off]; }
        __syncthreads();
    }
    if (t == 0) {
        float mean = (float)(ss[0] * invN);
        float var  = (float)(qq[0] * invN) - mean * mean;
        float inv  = rsqrtf(var + 1e-5f);
        float sc   = gamma[j] * inv;
        g_scale[j] = sc;
        g_shift[j] = beta[j] - mean * sc;
    }
}

// ---------------------------------------------------------------------------
// K5: out = relu(scale*h1 + shift) @ W2^T + b2.
// i = tid&63 (channel), hh = tid>>6 (warp-uniform K-half). Single smem buffer
// (2 syncs/iter), staging LDG prefetched across the compute phase.
// ---------------------------------------------------------------------------
__global__ void __launch_bounds__(128, 5) k_gemm2(const float* __restrict__ W2,  // [64,128]
                                                  const float* __restrict__ b2,
                                                  float* __restrict__ out,
                                                  int N)
{
    __shared__ float4 ash[8 * 32];      // 8 rows x 128 activations
    __shared__ float  sc[128], sh[128];
    __shared__ float  partial[8 * 64];
    int tid = threadIdx.x;
    int i  = tid & 63;
    int hh = tid >> 6;

    float4 w[16];
#pragma unroll
    for (int k4 = 0; k4 < 16; k4++)
        w[k4] = ((const float4*)W2)[i * 32 + hh * 16 + k4];
    sc[tid] = g_scale[tid];
    sh[tid] = g_shift[tid];
    float bi = __ldg(b2 + i);
    __syncthreads();

    long long step = (long long)GRID1 * 8;
    long long r0 = (long long)blockIdx.x * 8;

    // prefetch tile 0 (raw h1; scale/relu applied at STS time)
    float4 v[2];
#pragma unroll
    for (int t = 0; t < 2; t++) {
        int idx = tid + t * 128;
        long long row = r0 + (idx >> 5);
        v[t] = (row < N) ? ((const float4*)g_h1)[row * 32 + (idx & 31)]
                         : make_float4(0.f, 0.f, 0.f, 0.f);
    }

    for (; r0 < N; r0 += step) {
#pragma unroll
        for (int t = 0; t < 2; t++) {
            int idx = tid + t * 128;
            int j = (idx & 31) * 4;
            float4 a;
            a.x = fmaxf(fmaf(sc[j + 0], v[t].x, sh[j + 0]), 0.0f);
            a.y = fmaxf(fmaf(sc[j + 1], v[t].y, sh[j + 1]), 0.0f);
            a.z = fmaxf(fmaf(sc[j + 2], v[t].z, sh[j + 2]), 0.0f);
            a.w = fmaxf(fmaf(sc[j + 3], v[t].w, sh[j + 3]), 0.0f);
            ash[idx] = a;
        }
        __syncthreads();

        // prefetch next tile
        long long rn = r0 + step;
#pragma unroll
        for (int t = 0; t < 2; t++) {
            int idx = tid + t * 128;
            long long row = rn + (idx >> 5);
            v[t] = (row < N) ? ((const float4*)g_h1)[row * 32 + (idx & 31)]
                             : make_float4(0.f, 0.f, 0.f, 0.f);
        }

        float acc[8];
#pragma unroll
        for (int r = 0; r < 8; r++) acc[r] = 0.0f;
#pragma unroll
        for (int k4 = 0; k4 < 16; k4++) {
            float4 wv = w[k4];
#pragma unroll
            for (int r = 0; r < 8; r++) {
                float4 h = ash[r * 32 + hh * 16 + k4];  // warp-uniform: broadcast
                acc[r] += wv.x * h.x + wv.y * h.y + wv.z * h.z + wv.w * h.w;
            }
        }

        if (hh == 1) {
#pragma unroll
            for (int r = 0; r < 8; r++) partial[r * 64 + i] = acc[r];
        }
        __syncthreads();
        if (hh == 0) {
#pragma unroll
            for (int r = 0; r < 8; r++) {
                if (r0 + r < N)
                    out[(r0 + r) * 64 + i] = acc[r] + partial[r * 64 + i] + bi;
            }
        }
    }
}

// ---------------------------------------------------------------------------
// Binding: size-driven anchor on the unique size-320 buffer (bond_emb0).
// ---------------------------------------------------------------------------
extern "C" void kernel_launch(void* const* d_in, const int* in_sizes, int n_in,
                              void* d_out, int out_size)
{
    const float* nf = (const float*)d_in[0];
    const void*  ef = d_in[1];
    const void*  ei = d_in[2];

    int iEmb0 = -1;
    for (int i = 3; i < n_in; i++) {
        if (in_sizes[i] == 320) { iEmb0 = i; break; }
    }
    if (iEmb0 < 0) iEmb0 = 6;

    const float* eps   = (const float*)d_in[iEmb0 - 1];
    const float* e0    = (const float*)d_in[iEmb0];
    const float* e1    = (const float*)d_in[iEmb0 + 1];
    const float* e2    = (const float*)d_in[iEmb0 + 2];
    const float* W1    = (const float*)d_in[iEmb0 + 3];
    const float* b1    = (const float*)d_in[iEmb0 + 4];
    const float* gamma = (const float*)d_in[iEmb0 + 5];
    const float* beta  = (const float*)d_in[iEmb0 + 6];
    const float* W2    = (const float*)d_in[iEmb0 + 7];
    const float* b2    = (const float*)d_in[iEmb0 + 8];

    int N = in_sizes[0] / 64;
    long long E = (long long)in_sizes[1] / 3;

    k_probe<<<1, 1>>>((const long long*)ef);

    int n4 = N * 16;
    k_init<<<(n4 + 255) / 256, 256>>>(nf, eps, n4);

    long long warpsNeeded = (E + 1) / 2;
    int eblocks = (int)((warpsNeeded + 7) / 8);
    k_edge<<<eblocks, 256>>>((const float4*)nf, ef, ei,
                             (const float4*)e0, (const float4*)e1, (const float4*)e2, E, N);

    k_gemm1<<<GRID1, 128>>>(W1, b1, N);
    k_bn<<<128, 256>>>(gamma, beta, 1.0 / (double)N);
    k_gemm2<<<GRID1, 128>>>(W2, b2, (float*)d_out, N);
}

// round 9
// speedup vs baseline: 1.1008x; 1.1008x over previous
#include <cuda_runtime.h>
#include <cstdint>

#define MAXN 100000
#define DD 64
#define GRID1 592   // 4 waves of 148 SMs for both GEMM kernels

// ---- scratch (no allocations allowed) ----
__device__ __align__(16) float  g_hbuf[(size_t)MAXN * DD];   // h = (1+eps)*x + scatter [N,64]
__device__ __align__(16) float  g_h1[(size_t)MAXN * 2 * DD]; // pre-BN hidden           [N,128]
__device__ float  g_psum[128 * GRID1];                       // BN partials, TRANSPOSED [ch][blk]
__device__ float  g_psq [128 * GRID1];
__device__ float  g_scale[2 * DD];
__device__ float  g_shift[2 * DD];
__device__ int    g_is64;                                    // 1 if edge buffers are int64

// ---------------------------------------------------------------------------
// K0: dtype probe. edge_feats values are tiny (0/1). Read 32 int64 words:
// if all in [0,7] -> data really is int64; else it was downcast to int32.
// ---------------------------------------------------------------------------
__global__ void k_probe(const long long* __restrict__ ef)
{
    int ok = 1;
#pragma unroll
    for (int i = 0; i < 32; i++) {
        long long v = ef[i];
        if (v < 0 || v > 7) ok = 0;
    }
    g_is64 = ok;
}

// ---------------------------------------------------------------------------
// K1: h = (1+eps)*node_feats
// ---------------------------------------------------------------------------
__global__ void k_init(const float* __restrict__ nf, const float* __restrict__ eps, int n4)
{
    int i = blockIdx.x * blockDim.x + threadIdx.x;
    if (i < n4) {
        float s = 1.0f + eps[0];
        float4 v = ((const float4*)nf)[i];
        v.x *= s; v.y *= s; v.z *= s; v.w *= s;
        ((float4*)g_hbuf)[i] = v;
    }
}

// ---------------------------------------------------------------------------
// K2: edge messages + scatter-add.  2 edges per warp, 16 lanes x float4 each.
// ---------------------------------------------------------------------------
__global__ void k_edge(const float4* __restrict__ nf4,
                       const void* __restrict__ ef,    // [E,3]
                       const void* __restrict__ ei,    // [2,E]: row0=dst, row1=src
                       const float4* __restrict__ e0,
                       const float4* __restrict__ e1,
                       const float4* __restrict__ e2,
                       long long E, int Nn)
{
    int lane = threadIdx.x & 31;
    long long warpId = (long long)blockIdx.x * (blockDim.x >> 5) + (threadIdx.x >> 5);
    int half = lane >> 4;
    int q    = lane & 15;
    long long e = warpId * 2 + half;

    int src = 0, dst = 0, f0 = 0, f1 = 0, f2 = 0;
    if (q == 0 && e < E) {
        if (g_is64) {
            const long long* ei64 = (const long long*)ei;
            const long long* ef64 = (const long long*)ef + e * 3;
            dst = (int)ei64[e];
            src = (int)ei64[E + e];
            f0 = (int)ef64[0]; f1 = (int)ef64[1]; f2 = (int)ef64[2];
        } else {
            const int* ei32 = (const int*)ei;
            const int* ef32 = (const int*)ef + e * 3;
            dst = ei32[e];
            src = ei32[E + e];
            f0 = ef32[0]; f1 = ef32[1]; f2 = ef32[2];
        }
    }
    int leader = half << 4;
    dst = __shfl_sync(0xffffffffu, dst, leader);
    src = __shfl_sync(0xffffffffu, src, leader);
    f0  = __shfl_sync(0xffffffffu, f0,  leader);
    f1  = __shfl_sync(0xffffffffu, f1,  leader);
    f2  = __shfl_sync(0xffffffffu, f2,  leader);
    if (e >= E) return;
    if ((unsigned)src >= (unsigned)Nn || (unsigned)dst >= (unsigned)Nn) return;
    if ((unsigned)f0 > 4u || (unsigned)f1 > 5u || (unsigned)f2 > 1u) return;

    float4 a = e0[f0 * 16 + q];
    float4 b = e1[f1 * 16 + q];
    float4 c = e2[f2 * 16 + q];
    float4 n = nf4[(long long)src * 16 + q];

    float x = fmaxf(n.x + a.x + b.x + c.x, 0.0f);
    float y = fmaxf(n.y + a.y + b.y + c.y, 0.0f);
    float z = fmaxf(n.z + a.z + b.z + c.z, 0.0f);
    float w = fmaxf(n.w + a.w + b.w + c.w, 0.0f);

    float* p = g_hbuf + (long long)dst * 64 + q * 4;
    asm volatile("red.global.add.v4.f32 [%0], {%1,%2,%3,%4};"
                 :: "l"(p), "f"(x), "f"(y), "f"(z), "f"(w) : "memory");
}

// ---------------------------------------------------------------------------
// K3 v4: h1 = h @ W1^T + b1 + BN partial stats.
// Thread = (channel PAIR p = tid>>1, K-half kh = tid&1): 2 channels x 32 K
// values in registers (16 float4). Each h float4 loaded from smem now feeds
// 8 FMAs (2 channels) -> LDS instruction count HALVED vs v3.
// K-halves combined with shfl_xor(1) (same warp). Stored channel = tid.
// Double-buffered staging + prefetch, one sync/iter.
// ---------------------------------------------------------------------------
__global__ void __launch_bounds__(128) k_gemm1(const float* __restrict__ W1,  // [128,64]
                                               const float* __restrict__ b1,
                                               int N)
{
    __shared__ float4 hsh[2][8 * 16];  // double buffer: 8 rows x 64 floats
    int tid = threadIdx.x;
    int p  = tid >> 1;         // channel pair 0..63
    int kh = tid & 1;          // K-half 0/1
    int rowoff = tid >> 4;     // staging: row 0..7
    int kslot  = tid & 15;     // staging: float4 slot

    float4 w0[8], w1[8];
#pragma unroll
    for (int k4 = 0; k4 < 8; k4++) {
        w0[k4] = ((const float4*)W1)[(2 * p + 0) * 16 + kh * 8 + k4];
        w1[k4] = ((const float4*)W1)[(2 * p + 1) * 16 + kh * 8 + k4];
    }
    float bj = __ldg(b1 + tid);   // bias for stored channel (= tid)

    float lsum = 0.0f, lsq = 0.0f;

    long long step = (long long)GRID1 * 8;
    long long r0 = (long long)blockIdx.x * 8;

    // prefetch tile 0
    float4 v = make_float4(0.f, 0.f, 0.f, 0.f);
    if (r0 + rowoff < N) v = ((const float4*)g_hbuf)[(r0 + rowoff) * 16 + kslot];

    int buf = 0;
    for (; r0 < N; r0 += step) {
        hsh[buf][tid] = v;
        __syncthreads();

        // prefetch next tile (overlaps with compute below)
        long long rn = r0 + step;
        if (rn + rowoff < N) v = ((const float4*)g_hbuf)[(rn + rowoff) * 16 + kslot];
        else                 v = make_float4(0.f, 0.f, 0.f, 0.f);

        float a0[8], a1[8];
#pragma unroll
        for (int r = 0; r < 8; r++) { a0[r] = 0.0f; a1[r] = 0.0f; }
#pragma unroll
        for (int k4 = 0; k4 < 8; k4++) {
            float4 wv0 = w0[k4];
            float4 wv1 = w1[k4];
#pragma unroll
            for (int r = 0; r < 8; r++) {
                float4 h = hsh[buf][r * 16 + kh * 8 + k4];
                a0[r] += wv0.x * h.x + wv0.y * h.y + wv0.z * h.z + wv0.w * h.w;
                a1[r] += wv1.x * h.x + wv1.y * h.y + wv1.z * h.z + wv1.w * h.w;
            }
        }

        long long base = r0 * 128 + tid;
#pragma unroll
        for (int r = 0; r < 8; r++) {
            float f0 = a0[r] + __shfl_xor_sync(0xffffffffu, a0[r], 1);
            float f1 = a1[r] + __shfl_xor_sync(0xffffffffu, a1[r], 1);
            float val = (kh ? f1 : f0) + bj;     // channel 2p+kh == tid
            if (r0 + r < N) {
                g_h1[base + r * 128] = val;
                lsum += val; lsq += val * val;
            }
        }
        buf ^= 1;
    }
    g_psum[tid * GRID1 + blockIdx.x] = lsum;   // transposed: [channel][block]
    g_psq [tid * GRID1 + blockIdx.x] = lsq;
}

// ---------------------------------------------------------------------------
// K4 v3: 128 blocks (one per channel) x 256 threads; coalesced per-channel
// reduction of GRID1 partials, double accumulation, fold into scale/shift.
// ---------------------------------------------------------------------------
__global__ void __launch_bounds__(256) k_bn(const float* __restrict__ gamma,
                                            const float* __restrict__ beta,
                                            double invN)
{
    __shared__ double ss[256], qq[256];
    int j = blockIdx.x;
    int t = threadIdx.x;

    double s = 0.0, q = 0.0;
    for (int b = t; b < GRID1; b += 256) {
        s += (double)g_psum[j * GRID1 + b];
        q += (double)g_psq [j * GRID1 + b];
    }
    ss[t] = s; qq[t] = q;
    __syncthreads();
    for (int off = 128; off > 0; off >>= 1) {
        if (t < off) { ss[t] += ss[t + off]; qq[t] += qq[t + off]; }
        __syncthreads();
    }
    if (t == 0) {
        float mean = (float)(ss[0] * invN);
        float var  = (float)(qq[0] * invN) - mean * mean;
        float inv  = rsqrtf(var + 1e-5f);
        float sc   = gamma[j] * inv;
        g_scale[j] = sc;
        g_shift[j] = beta[j] - mean * sc;
    }
}

// ---------------------------------------------------------------------------
// K5: out = relu(scale*h1 + shift) @ W2^T + b2.  (R5-best form)
// i = tid&63 (channel), hh = tid>>6 (warp-uniform K-half). Single smem buffer
// (2 syncs/iter), staging LDG prefetched across the compute phase.
// ---------------------------------------------------------------------------
__global__ void __launch_bounds__(128) k_gemm2(const float* __restrict__ W2,  // [64,128]
                                               const float* __restrict__ b2,
                                               float* __restrict__ out,
                                               int N)
{
    __shared__ float4 ash[8 * 32];      // 8 rows x 128 activations
    __shared__ float  sc[128], sh[128];
    __shared__ float  partial[8 * 64];
    int tid = threadIdx.x;
    int i  = tid & 63;
    int hh = tid >> 6;

    float4 w[16];
#pragma unroll
    for (int k4 = 0; k4 < 16; k4++)
        w[k4] = ((const float4*)W2)[i * 32 + hh * 16 + k4];
    sc[tid] = g_scale[tid];
    sh[tid] = g_shift[tid];
    float bi = __ldg(b2 + i);
    __syncthreads();

    long long step = (long long)GRID1 * 8;
    long long r0 = (long long)blockIdx.x * 8;

    // prefetch tile 0 (raw h1; scale/relu applied at STS time)
    float4 v[2];
#pragma unroll
    for (int t = 0; t < 2; t++) {
        int idx = tid + t * 128;
        long long row = r0 + (idx >> 5);
        v[t] = (row < N) ? ((const float4*)g_h1)[row * 32 + (idx & 31)]
                         : make_float4(0.f, 0.f, 0.f, 0.f);
    }

    for (; r0 < N; r0 += step) {
#pragma unroll
        for (int t = 0; t < 2; t++) {
            int idx = tid + t * 128;
            int j = (idx & 31) * 4;
            float4 a;
            a.x = fmaxf(fmaf(sc[j + 0], v[t].x, sh[j + 0]), 0.0f);
            a.y = fmaxf(fmaf(sc[j + 1], v[t].y, sh[j + 1]), 0.0f);
            a.z = fmaxf(fmaf(sc[j + 2], v[t].z, sh[j + 2]), 0.0f);
            a.w = fmaxf(fmaf(sc[j + 3], v[t].w, sh[j + 3]), 0.0f);
            ash[idx] = a;
        }
        __syncthreads();

        // prefetch next tile
        long long rn = r0 + step;
#pragma unroll
        for (int t = 0; t < 2; t++) {
            int idx = tid + t * 128;
            long long row = rn + (idx >> 5);
            v[t] = (row < N) ? ((const float4*)g_h1)[row * 32 + (idx & 31)]
                             : make_float4(0.f, 0.f, 0.f, 0.f);
        }

        float acc[8];
#pragma unroll
        for (int r = 0; r < 8; r++) acc[r] = 0.0f;
#pragma unroll
        for (int k4 = 0; k4 < 16; k4++) {
            float4 wv = w[k4];
#pragma unroll
            for (int r = 0; r < 8; r++) {
                float4 h = ash[r * 32 + hh * 16 + k4];  // warp-uniform: broadcast
                acc[r] += wv.x * h.x + wv.y * h.y + wv.z * h.z + wv.w * h.w;
            }
        }

        if (hh == 1) {
#pragma unroll
            for (int r = 0; r < 8; r++) partial[r * 64 + i] = acc[r];
        }
        __syncthreads();
        if (hh == 0) {
#pragma unroll
            for (int r = 0; r < 8; r++) {
                if (r0 + r < N)
                    out[(r0 + r) * 64 + i] = acc[r] + partial[r * 64 + i] + bi;
            }
        }
    }
}

// ---------------------------------------------------------------------------
// Binding: size-driven anchor on the unique size-320 buffer (bond_emb0).
// ---------------------------------------------------------------------------
extern "C" void kernel_launch(void* const* d_in, const int* in_sizes, int n_in,
                              void* d_out, int out_size)
{
    const float* nf = (const float*)d_in[0];
    const void*  ef = d_in[1];
    const void*  ei = d_in[2];

    int iEmb0 = -1;
    for (int i = 3; i < n_in; i++) {
        if (in_sizes[i] == 320) { iEmb0 = i; break; }
    }
    if (iEmb0 < 0) iEmb0 = 6;

    const float* eps   = (const float*)d_in[iEmb0 - 1];
    const float* e0    = (const float*)d_in[iEmb0];
    const float* e1    = (const float*)d_in[iEmb0 + 1];
    const float* e2    = (const float*)d_in[iEmb0 + 2];
    const float* W1    = (const float*)d_in[iEmb0 + 3];
    const float* b1    = (const float*)d_in[iEmb0 + 4];
    const float* gamma = (const float*)d_in[iEmb0 + 5];
    const float* beta  = (const float*)d_in[iEmb0 + 6];
    const float* W2    = (const float*)d_in[iEmb0 + 7];
    const float* b2    = (const float*)d_in[iEmb0 + 8];

    int N = in_sizes[0] / 64;
    long long E = (long long)in_sizes[1] / 3;

    k_probe<<<1, 1>>>((const long long*)ef);

    int n4 = N * 16;
    k_init<<<(n4 + 255) / 256, 256>>>(nf, eps, n4);

    long long warpsNeeded = (E + 1) / 2;
    int eblocks = (int)((warpsNeeded + 7) / 8);
    k_edge<<<eblocks, 256>>>((const float4*)nf, ef, ei,
                             (const float4*)e0, (const float4*)e1, (const float4*)e2, E, N);

    k_gemm1<<<GRID1, 128>>>(W1, b1, N);
    k_bn<<<128, 256>>>(gamma, beta, 1.0 / (double)N);
    k_gemm2<<<GRID1, 128>>>(W2, b2, (float*)d_out, N);
}

// round 13
// speedup vs baseline: 1.2315x; 1.1187x over previous
#include <cuda_runtime.h>
#include <cstdint>

#define MAXN 100000
#define MAXE 1600000
#define DD 64
#define GRID1 592   // 4 waves of 148 SMs for both GEMM kernels

// ---- scratch (no allocations allowed) ----
__device__ __align__(16) float  g_hbuf[(size_t)MAXN * DD];   // h = (1+eps)*x + gathered sum [N,64]
__device__ __align__(16) float  g_h1[(size_t)MAXN * 2 * DD]; // pre-BN hidden                [N,128]
__device__ float  g_psum[128 * GRID1];                       // BN partials, TRANSPOSED [ch][blk]
__device__ float  g_psq [128 * GRID1];
__device__ float  g_scale[2 * DD];
__device__ float  g_shift[2 * DD];
__device__ int    g_is64;                                    // 1 if edge buffers are int64
// CSR-by-dst scratch
__device__ int    g_rowptr[MAXN + 1];
__device__ int    g_cursor[MAXN];          // doubles as degree histogram
__device__ int    g_bsum[128];             // per-block scan totals (<=98 used)
__device__ int    g_boff[128];
__device__ int    g_payload[MAXE];         // src(17b) | f0(3b) | f1(3b) | f2(1b)

// ---------------------------------------------------------------------------
// K0: dtype probe. edge_feats values are tiny (0/1). Read 32 int64 words:
// if all in [0,7] -> data really is int64; else downcast to int32.
// ---------------------------------------------------------------------------
__global__ void k_probe(const long long* __restrict__ ef)
{
    int ok = 1;
#pragma unroll
    for (int i = 0; i < 32; i++) {
        long long v = ef[i];
        if (v < 0 || v > 7) ok = 0;
    }
    g_is64 = ok;
}

// ---------------------------------------------------------------------------
// CSR build step 1: zero degree histogram
// ---------------------------------------------------------------------------
__global__ void k_zero(int N)
{
    int i = blockIdx.x * blockDim.x + threadIdx.x;
    if (i < N) g_cursor[i] = 0;
}

// ---------------------------------------------------------------------------
// CSR build step 2: degree histogram over dst (= edge_index row 0)
// ---------------------------------------------------------------------------
__global__ void k_hist(const void* __restrict__ ei, long long E, int Nn)
{
    long long e = (long long)blockIdx.x * blockDim.x + threadIdx.x;
    if (e >= E) return;
    int dst = g_is64 ? (int)((const long long*)ei)[e] : ((const int*)ei)[e];
    if ((unsigned)dst < (unsigned)Nn) atomicAdd(&g_cursor[dst], 1);
}

// ---------------------------------------------------------------------------
// CSR build step 3a: per-1024-block exclusive scan of degrees
// ---------------------------------------------------------------------------
__global__ void __launch_bounds__(1024) k_scanA(int N)
{
    __shared__ int sh[1024];
    int t = threadIdx.x;
    int idx = blockIdx.x * 1024 + t;
    int x = (idx < N) ? g_cursor[idx] : 0;
    sh[t] = x;
    __syncthreads();
    for (int off = 1; off < 1024; off <<= 1) {
        int v = (t >= off) ? sh[t - off] : 0;
        __syncthreads();
        sh[t] += v;
        __syncthreads();
    }
    if (idx < N) g_rowptr[idx] = sh[t] - x;      // exclusive, pre-offset
    if (t == 1023) g_bsum[blockIdx.x] = sh[1023];
}

// ---------------------------------------------------------------------------
// CSR build step 3b: scan block totals (single block, 128 lanes)
// ---------------------------------------------------------------------------
__global__ void __launch_bounds__(128) k_scanB(int nblk)
{
    __shared__ int sh[128];
    int t = threadIdx.x;
    int x = (t < nblk) ? g_bsum[t] : 0;
    sh[t] = x;
    __syncthreads();
    for (int off = 1; off < 128; off <<= 1) {
        int v = (t >= off) ? sh[t - off] : 0;
        __syncthreads();
        sh[t] += v;
        __syncthreads();
    }
    g_boff[t] = sh[t] - x;                        // exclusive
}

// ---------------------------------------------------------------------------
// CSR build step 3c: add block offsets; init cursor; close rowptr
// ---------------------------------------------------------------------------
__global__ void k_scanC(int N, int E)
{
    int i = blockIdx.x * blockDim.x + threadIdx.x;
    if (i < N) {
        int v = g_rowptr[i] + g_boff[i >> 10];
        g_rowptr[i] = v;
        g_cursor[i] = v;
    }
    if (i == 0) g_rowptr[N] = E;
}

// ---------------------------------------------------------------------------
// CSR build step 4: fill payload (src + packed bond features)
// ---------------------------------------------------------------------------
__global__ void k_fill(const void* __restrict__ ef, const void* __restrict__ ei,
                       long long E, int Nn)
{
    long long e = (long long)blockIdx.x * blockDim.x + threadIdx.x;
    if (e >= E) return;
    int dst, src, f0, f1, f2;
    if (g_is64) {
        const long long* ei64 = (const long long*)ei;
        const long long* ef64 = (const long long*)ef + e * 3;
        dst = (int)ei64[e]; src = (int)ei64[E + e];
        f0 = (int)ef64[0]; f1 = (int)ef64[1]; f2 = (int)ef64[2];
    } else {
        const int* ei32 = (const int*)ei;
        const int* ef32 = (const int*)ef + e * 3;
        dst = ei32[e]; src = ei32[E + e];
        f0 = ef32[0]; f1 = ef32[1]; f2 = ef32[2];
    }
    if ((unsigned)dst >= (unsigned)Nn || (unsigned)src >= (unsigned)Nn) return;
    int pos = atomicAdd(&g_cursor[dst], 1);
    if (pos < MAXE)
        g_payload[pos] = (src & 0x1FFFF) | ((f0 & 7) << 17) | ((f1 & 7) << 20) | ((f2 & 1) << 23);
}

// ---------------------------------------------------------------------------
// K_gather: per-node register reduction (replaces scatter atomics + k_init).
// 16 lanes per node, lane q holds float4 slot q.
// h[node] = (1+eps)*nf[node] + sum_edges relu(nf[src]+emb0+emb1+emb2)
// 2-way edge unroll for MLP.
// ---------------------------------------------------------------------------
__global__ void __launch_bounds__(256) k_gather(const float4* __restrict__ nf4,
                                                const float4* __restrict__ e0,
                                                const float4* __restrict__ e1,
                                                const float4* __restrict__ e2,
                                                const float* __restrict__ eps,
                                                int Nn)
{
    int gid  = blockIdx.x * 16 + (threadIdx.x >> 4);   // node id
    int q    = threadIdx.x & 15;
    if (gid >= Nn) return;

    int beg = g_rowptr[gid];
    int end = g_rowptr[gid + 1];

    float s = 1.0f + __ldg(eps);
    float4 acc = nf4[(long long)gid * 16 + q];
    acc.x *= s; acc.y *= s; acc.z *= s; acc.w *= s;

    int i = beg;
    for (; i + 2 <= end; i += 2) {
        int p0 = g_payload[i];
        int p1 = g_payload[i + 1];
        int s0 = p0 & 0x1FFFF, s1 = p1 & 0x1FFFF;
        float4 n0 = nf4[(long long)s0 * 16 + q];
        float4 n1 = nf4[(long long)s1 * 16 + q];
        float4 a0 = e0[((p0 >> 17) & 7) * 16 + q];
        float4 b0 = e1[((p0 >> 20) & 7) * 16 + q];
        float4 c0 = e2[((p0 >> 23) & 1) * 16 + q];
        float4 a1 = e0[((p1 >> 17) & 7) * 16 + q];
        float4 b1 = e1[((p1 >> 20) & 7) * 16 + q];
        float4 c1 = e2[((p1 >> 23) & 1) * 16 + q];
        acc.x += fmaxf(n0.x + a0.x + b0.x + c0.x, 0.0f) + fmaxf(n1.x + a1.x + b1.x + c1.x, 0.0f);
        acc.y += fmaxf(n0.y + a0.y + b0.y + c0.y, 0.0f) + fmaxf(n1.y + a1.y + b1.y + c1.y, 0.0f);
        acc.z += fmaxf(n0.z + a0.z + b0.z + c0.z, 0.0f) + fmaxf(n1.z + a1.z + b1.z + c1.z, 0.0f);
        acc.w += fmaxf(n0.w + a0.w + b0.w + c0.w, 0.0f) + fmaxf(n1.w + a1.w + b1.w + c1.w, 0.0f);
    }
    if (i < end) {
        int p0 = g_payload[i];
        int s0 = p0 & 0x1FFFF;
        float4 n0 = nf4[(long long)s0 * 16 + q];
        float4 a0 = e0[((p0 >> 17) & 7) * 16 + q];
        float4 b0 = e1[((p0 >> 20) & 7) * 16 + q];
        float4 c0 = e2[((p0 >> 23) & 1) * 16 + q];
        acc.x += fmaxf(n0.x + a0.x + b0.x + c0.x, 0.0f);
        acc.y += fmaxf(n0.y + a0.y + b0.y + c0.y, 0.0f);
        acc.z += fmaxf(n0.z + a0.z + b0.z + c0.z, 0.0f);
        acc.w += fmaxf(n0.w + a0.w + b0.w + c0.w, 0.0f);
    }
    ((float4*)g_hbuf)[(long long)gid * 16 + q] = acc;
}

// ---------------------------------------------------------------------------
// K3: h1 = h @ W1^T + b1 + BN partials. (R9 form: 2ch x half-K per thread)
// ---------------------------------------------------------------------------
__global__ void __launch_bounds__(128) k_gemm1(const float* __restrict__ W1,  // [128,64]
                                               const float* __restrict__ b1,
                                               int N)
{
    __shared__ float4 hsh[2][8 * 16];
    int tid = threadIdx.x;
    int p  = tid >> 1;
    int kh = tid & 1;
    int rowoff = tid >> 4;
    int kslot  = tid & 15;

    float4 w0[8], w1[8];
#pragma unroll
    for (int k4 = 0; k4 < 8; k4++) {
        w0[k4] = ((const float4*)W1)[(2 * p + 0) * 16 + kh * 8 + k4];
        w1[k4] = ((const float4*)W1)[(2 * p + 1) * 16 + kh * 8 + k4];
    }
    float bj = __ldg(b1 + tid);

    float lsum = 0.0f, lsq = 0.0f;

    long long step = (long long)GRID1 * 8;
    long long r0 = (long long)blockIdx.x * 8;

    float4 v = make_float4(0.f, 0.f, 0.f, 0.f);
    if (r0 + rowoff < N) v = ((const float4*)g_hbuf)[(r0 + rowoff) * 16 + kslot];

    int buf = 0;
    for (; r0 < N; r0 += step) {
        hsh[buf][tid] = v;
        __syncthreads();

        long long rn = r0 + step;
        if (rn + rowoff < N) v = ((const float4*)g_hbuf)[(rn + rowoff) * 16 + kslot];
        else                 v = make_float4(0.f, 0.f, 0.f, 0.f);

        float a0[8], a1[8];
#pragma unroll
        for (int r = 0; r < 8; r++) { a0[r] = 0.0f; a1[r] = 0.0f; }
#pragma unroll
        for (int k4 = 0; k4 < 8; k4++) {
            float4 wv0 = w0[k4];
            float4 wv1 = w1[k4];
#pragma unroll
            for (int r = 0; r < 8; r++) {
                float4 h = hsh[buf][r * 16 + kh * 8 + k4];
                a0[r] += wv0.x * h.x + wv0.y * h.y + wv0.z * h.z + wv0.w * h.w;
                a1[r] += wv1.x * h.x + wv1.y * h.y + wv1.z * h.z + wv1.w * h.w;
            }
        }

        long long base = r0 * 128 + tid;
#pragma unroll
        for (int r = 0; r < 8; r++) {
            float f0 = a0[r] + __shfl_xor_sync(0xffffffffu, a0[r], 1);
            float f1 = a1[r] + __shfl_xor_sync(0xffffffffu, a1[r], 1);
            float val = (kh ? f1 : f0) + bj;
            if (r0 + r < N) {
                g_h1[base + r * 128] = val;
                lsum += val; lsq += val * val;
            }
        }
        buf ^= 1;
    }
    g_psum[tid * GRID1 + blockIdx.x] = lsum;
    g_psq [tid * GRID1 + blockIdx.x] = lsq;
}

// ---------------------------------------------------------------------------
// K4: 128 blocks x 256 threads; coalesced BN reduction -> scale/shift.
// ---------------------------------------------------------------------------
__global__ void __launch_bounds__(256) k_bn(const float* __restrict__ gamma,
                                            const float* __restrict__ beta,
                                            double invN)
{
    __shared__ double ss[256], qq[256];
    int j = blockIdx.x;
    int t = threadIdx.x;

    double s = 0.0, q = 0.0;
    for (int b = t; b < GRID1; b += 256) {
        s += (double)g_psum[j * GRID1 + b];
        q += (double)g_psq [j * GRID1 + b];
    }
    ss[t] = s; qq[t] = q;
    __syncthreads();
    for (int off = 128; off > 0; off >>= 1) {
        if (t < off) { ss[t] += ss[t + off]; qq[t] += qq[t + off]; }
        __syncthreads();
    }
    if (t == 0) {
        float mean = (float)(ss[0] * invN);
        float var  = (float)(qq[0] * invN) - mean * mean;
        float inv  = rsqrtf(var + 1e-5f);
        float sc   = gamma[j] * inv;
        g_scale[j] = sc;
        g_shift[j] = beta[j] - mean * sc;
    }
}

// ---------------------------------------------------------------------------
// K5: out = relu(scale*h1 + shift) @ W2^T + b2. (R5-best form)
// ---------------------------------------------------------------------------
__global__ void __launch_bounds__(128) k_gemm2(const float* __restrict__ W2,  // [64,128]
                                               const float* __restrict__ b2,
                                               float* __restrict__ out,
                                               int N)
{
    __shared__ float4 ash[8 * 32];
    __shared__ float  sc[128], sh[128];
    __shared__ float  partial[8 * 64];
    int tid = threadIdx.x;
    int i  = tid & 63;
    int hh = tid >> 6;

    float4 w[16];
#pragma unroll
    for (int k4 = 0; k4 < 16; k4++)
        w[k4] = ((const float4*)W2)[i * 32 + hh * 16 + k4];
    sc[tid] = g_scale[tid];
    sh[tid] = g_shift[tid];
    float bi = __ldg(b2 + i);
    __syncthreads();

    long long step = (long long)GRID1 * 8;
    long long r0 = (long long)blockIdx.x * 8;

    float4 v[2];
#pragma unroll
    for (int t = 0; t < 2; t++) {
        int idx = tid + t * 128;
        long long row = r0 + (idx >> 5);
        v[t] = (row < N) ? ((const float4*)g_h1)[row * 32 + (idx & 31)]
                         : make_float4(0.f, 0.f, 0.f, 0.f);
    }

    for (; r0 < N; r0 += step) {
#pragma unroll
        for (int t = 0; t < 2; t++) {
            int idx = tid + t * 128;
            int j = (idx & 31) * 4;
            float4 a;
            a.x = fmaxf(fmaf(sc[j + 0], v[t].x, sh[j + 0]), 0.0f);
            a.y = fmaxf(fmaf(sc[j + 1], v[t].y, sh[j + 1]), 0.0f);
            a.z = fmaxf(fmaf(sc[j + 2], v[t].z, sh[j + 2]), 0.0f);
            a.w = fmaxf(fmaf(sc[j + 3], v[t].w, sh[j + 3]), 0.0f);
            ash[idx] = a;
        }
        __syncthreads();

        long long rn = r0 + step;
#pragma unroll
        for (int t = 0; t < 2; t++) {
            int idx = tid + t * 128;
            long long row = rn + (idx >> 5);
            v[t] = (row < N) ? ((const float4*)g_h1)[row * 32 + (idx & 31)]
                             : make_float4(0.f, 0.f, 0.f, 0.f);
        }

        float acc[8];
#pragma unroll
        for (int r = 0; r < 8; r++) acc[r] = 0.0f;
#pragma unroll
        for (int k4 = 0; k4 < 16; k4++) {
            float4 wv = w[k4];
#pragma unroll
            for (int r = 0; r < 8; r++) {
                float4 h = ash[r * 32 + hh * 16 + k4];
                acc[r] += wv.x * h.x + wv.y * h.y + wv.z * h.z + wv.w * h.w;
            }
        }

        if (hh == 1) {
#pragma unroll
            for (int r = 0; r < 8; r++) partial[r * 64 + i] = acc[r];
        }
        __syncthreads();
        if (hh == 0) {
#pragma unroll
            for (int r = 0; r < 8; r++) {
                if (r0 + r < N)
                    out[(r0 + r) * 64 + i] = acc[r] + partial[r * 64 + i] + bi;
            }
        }
    }
}

// ---------------------------------------------------------------------------
// Binding: size-driven anchor on the unique size-320 buffer (bond_emb0).
// ---------------------------------------------------------------------------
extern "C" void kernel_launch(void* const* d_in, const int* in_sizes, int n_in,
                              void* d_out, int out_size)
{
    const float* nf = (const float*)d_in[0];
    const void*  ef = d_in[1];
    const void*  ei = d_in[2];

    int iEmb0 = -1;
    for (int i = 3; i < n_in; i++) {
        if (in_sizes[i] == 320) { iEmb0 = i; break; }
    }
    if (iEmb0 < 0) iEmb0 = 6;

    const float* eps   = (const float*)d_in[iEmb0 - 1];
    const float* e0    = (const float*)d_in[iEmb0];
    const float* e1    = (const float*)d_in[iEmb0 + 1];
    const float* e2    = (const float*)d_in[iEmb0 + 2];
    const float* W1    = (const float*)d_in[iEmb0 + 3];
    const float* b1    = (const float*)d_in[iEmb0 + 4];
    const float* gamma = (const float*)d_in[iEmb0 + 5];
    const float* beta  = (const float*)d_in[iEmb0 + 6];
    const float* W2    = (const float*)d_in[iEmb0 + 7];
    const float* b2    = (const float*)d_in[iEmb0 + 8];

    int N = in_sizes[0] / 64;
    long long E = (long long)in_sizes[1] / 3;

    k_probe<<<1, 1>>>((const long long*)ef);

    // CSR build
    int nscan = (N + 1023) / 1024;
    k_zero<<<(N + 255) / 256, 256>>>(N);
    k_hist<<<(int)((E + 255) / 256), 256>>>(ei, E, N);
    k_scanA<<<nscan, 1024>>>(N);
    k_scanB<<<1, 128>>>(nscan);
    k_scanC<<<(N + 255) / 256, 256>>>(N, (int)E);
    k_fill<<<(int)((E + 255) / 256), 256>>>(ef, ei, E, N);

    // gather-reduce (also applies (1+eps)*x)
    k_gather<<<(N + 15) / 16, 256>>>((const float4*)nf,
                                     (const float4*)e0, (const float4*)e1, (const float4*)e2,
                                     eps, N);

    k_gemm1<<<GRID1, 128>>>(W1, b1, N);
    k_bn<<<128, 256>>>(gamma, beta, 1.0 / (double)N);
    k_gemm2<<<GRID1, 128>>>(W2, b2, (float*)d_out, N);
}

// round 16
// speedup vs baseline: 1.2960x; 1.0524x over previous
#include <cuda_runtime.h>
#include <cstdint>

#define MAXN 100000
#define MAXE 1600000
#define DD 64
#define GRID1 592   // 4 waves of 148 SMs for both GEMM kernels

// ---- scratch (no allocations allowed) ----
__device__ __align__(16) float  g_hbuf[(size_t)MAXN * DD];   // h = (1+eps)*x + gathered sum [N,64]
__device__ __align__(16) float  g_h1[(size_t)MAXN * 2 * DD]; // pre-BN hidden                [N,128]
__device__ float  g_psum[128 * GRID1];                       // BN partials, TRANSPOSED [ch][blk]
__device__ float  g_psq [128 * GRID1];
__device__ float  g_scale[2 * DD];
__device__ float  g_shift[2 * DD];
__device__ int    g_is64;                                    // 1 if edge buffers are int64
// CSR-by-dst scratch
__device__ int    g_rowptr[MAXN + 1];
__device__ int    g_cursor[MAXN];          // doubles as degree histogram
__device__ int    g_bsum[128];             // per-block scan totals (<=98 used)
__device__ int    g_boff[128];
__device__ int    g_payload[MAXE];         // src(17b) | f0(3b) | f1(3b) | f2(1b)

// ---------------------------------------------------------------------------
// K0: dtype probe.
// ---------------------------------------------------------------------------
__global__ void k_probe(const long long* __restrict__ ef)
{
    int ok = 1;
#pragma unroll
    for (int i = 0; i < 32; i++) {
        long long v = ef[i];
        if (v < 0 || v > 7) ok = 0;
    }
    g_is64 = ok;
}

// ---------------------------------------------------------------------------
// CSR build step 1: zero degree histogram
// ---------------------------------------------------------------------------
__global__ void k_zero(int N)
{
    int i = blockIdx.x * blockDim.x + threadIdx.x;
    if (i < N) g_cursor[i] = 0;
}

// ---------------------------------------------------------------------------
// CSR build step 2: degree histogram over dst (= edge_index row 0)
// ---------------------------------------------------------------------------
__global__ void k_hist(const void* __restrict__ ei, long long E, int Nn)
{
    long long e = (long long)blockIdx.x * blockDim.x + threadIdx.x;
    if (e >= E) return;
    int dst = g_is64 ? (int)((const long long*)ei)[e] : ((const int*)ei)[e];
    if ((unsigned)dst < (unsigned)Nn) atomicAdd(&g_cursor[dst], 1);
}

// ---------------------------------------------------------------------------
// CSR build step 3a: per-1024-block exclusive scan of degrees
// ---------------------------------------------------------------------------
__global__ void __launch_bounds__(1024) k_scanA(int N)
{
    __shared__ int sh[1024];
    int t = threadIdx.x;
    int idx = blockIdx.x * 1024 + t;
    int x = (idx < N) ? g_cursor[idx] : 0;
    sh[t] = x;
    __syncthreads();
    for (int off = 1; off < 1024; off <<= 1) {
        int v = (t >= off) ? sh[t - off] : 0;
        __syncthreads();
        sh[t] += v;
        __syncthreads();
    }
    if (idx < N) g_rowptr[idx] = sh[t] - x;      // exclusive, pre-offset
    if (t == 1023) g_bsum[blockIdx.x] = sh[1023];
}

// ---------------------------------------------------------------------------
// CSR build step 3b: scan block totals (single block, 128 lanes)
// ---------------------------------------------------------------------------
__global__ void __launch_bounds__(128) k_scanB(int nblk)
{
    __shared__ int sh[128];
    int t = threadIdx.x;
    int x = (t < nblk) ? g_bsum[t] : 0;
    sh[t] = x;
    __syncthreads();
    for (int off = 1; off < 128; off <<= 1) {
        int v = (t >= off) ? sh[t - off] : 0;
        __syncthreads();
        sh[t] += v;
        __syncthreads();
    }
    g_boff[t] = sh[t] - x;                        // exclusive
}

// ---------------------------------------------------------------------------
// CSR build step 3c: add block offsets; init cursor; close rowptr
// ---------------------------------------------------------------------------
__global__ void k_scanC(int N, int E)
{
    int i = blockIdx.x * blockDim.x + threadIdx.x;
    if (i < N) {
        int v = g_rowptr[i] + g_boff[i >> 10];
        g_rowptr[i] = v;
        g_cursor[i] = v;
    }
    if (i == 0) g_rowptr[N] = E;
}

// ---------------------------------------------------------------------------
// CSR build step 4: fill payload (src + packed bond features)
// ---------------------------------------------------------------------------
__global__ void k_fill(const void* __restrict__ ef, const void* __restrict__ ei,
                       long long E, int Nn)
{
    long long e = (long long)blockIdx.x * blockDim.x + threadIdx.x;
    if (e >= E) return;
    int dst, src, f0, f1, f2;
    if (g_is64) {
        const long long* ei64 = (const long long*)ei;
        const long long* ef64 = (const long long*)ef + e * 3;
        dst = (int)ei64[e]; src = (int)ei64[E + e];
        f0 = (int)ef64[0]; f1 = (int)ef64[1]; f2 = (int)ef64[2];
    } else {
        const int* ei32 = (const int*)ei;
        const int* ef32 = (const int*)ef + e * 3;
        dst = ei32[e]; src = ei32[E + e];
        f0 = ef32[0]; f1 = ef32[1]; f2 = ef32[2];
    }
    if ((unsigned)dst >= (unsigned)Nn || (unsigned)src >= (unsigned)Nn) return;
    int pos = atomicAdd(&g_cursor[dst], 1);
    if (pos < MAXE)
        g_payload[pos] = (src & 0x1FFFF) | ((f0 & 7) << 17) | ((f1 & 7) << 20) | ((f2 & 1) << 23);
}

// ---------------------------------------------------------------------------
// K_gather v2: per-node register reduction with smem COMBO TABLE.
// The 5x6x2 = 60 possible embedding sums are precomputed per block into
// shared memory (60 x 16 float4 = 15.4KB). Inner loop per edge-lane:
// 1 LDG (nf row) + 1 LDS (combo) instead of 4 LDG. 4-way edge unroll.
// h[node] = (1+eps)*nf[node] + sum relu(nf[src] + combo[f0,f1,f2])
// ---------------------------------------------------------------------------
__global__ void __launch_bounds__(256) k_gather(const float4* __restrict__ nf4,
                                                const float4* __restrict__ e0,
                                                const float4* __restrict__ e1,
                                                const float4* __restrict__ e2,
                                                const float* __restrict__ eps,
                                                int Nn)
{
    __shared__ float4 combo[60 * 16];
    for (int idx = threadIdx.x; idx < 60 * 16; idx += 256) {
        int c = idx >> 4, q = idx & 15;
        int f0 = c / 12, rem = c % 12;
        int f1 = rem >> 1, f2 = rem & 1;
        float4 a = e0[f0 * 16 + q];
        float4 b = e1[f1 * 16 + q];
        float4 d = e2[f2 * 16 + q];
        combo[idx] = make_float4(a.x + b.x + d.x, a.y + b.y + d.y,
                                 a.z + b.z + d.z, a.w + b.w + d.w);
    }
    __syncthreads();

    int gid = blockIdx.x * 16 + (threadIdx.x >> 4);   // node id
    int q   = threadIdx.x & 15;
    if (gid >= Nn) return;

    int beg = g_rowptr[gid];
    int end = g_rowptr[gid + 1];

    float s = 1.0f + __ldg(eps);
    float4 acc = nf4[(long long)gid * 16 + q];
    acc.x *= s; acc.y *= s; acc.z *= s; acc.w *= s;

    int i = beg;
#pragma unroll 1
    for (; i + 4 <= end; i += 4) {
        int p0 = g_payload[i];
        int p1 = g_payload[i + 1];
        int p2 = g_payload[i + 2];
        int p3 = g_payload[i + 3];
        float4 n0 = nf4[(long long)(p0 & 0x1FFFF) * 16 + q];
        float4 n1 = nf4[(long long)(p1 & 0x1FFFF) * 16 + q];
        float4 n2 = nf4[(long long)(p2 & 0x1FFFF) * 16 + q];
        float4 n3 = nf4[(long long)(p3 & 0x1FFFF) * 16 + q];
        int c0 = ((p0 >> 17) & 7) * 12 + ((p0 >> 20) & 7) * 2 + ((p0 >> 23) & 1);
        int c1 = ((p1 >> 17) & 7) * 12 + ((p1 >> 20) & 7) * 2 + ((p1 >> 23) & 1);
        int c2 = ((p2 >> 17) & 7) * 12 + ((p2 >> 20) & 7) * 2 + ((p2 >> 23) & 1);
        int c3 = ((p3 >> 17) & 7) * 12 + ((p3 >> 20) & 7) * 2 + ((p3 >> 23) & 1);
        float4 m0 = combo[c0 * 16 + q];
        float4 m1 = combo[c1 * 16 + q];
        float4 m2 = combo[c2 * 16 + q];
        float4 m3 = combo[c3 * 16 + q];
        acc.x += fmaxf(n0.x + m0.x, 0.f) + fmaxf(n1.x + m1.x, 0.f)
               + fmaxf(n2.x + m2.x, 0.f) + fmaxf(n3.x + m3.x, 0.f);
        acc.y += fmaxf(n0.y + m0.y, 0.f) + fmaxf(n1.y + m1.y, 0.f)
               + fmaxf(n2.y + m2.y, 0.f) + fmaxf(n3.y + m3.y, 0.f);
        acc.z += fmaxf(n0.z + m0.z, 0.f) + fmaxf(n1.z + m1.z, 0.f)
               + fmaxf(n2.z + m2.z, 0.f) + fmaxf(n3.z + m3.z, 0.f);
        acc.w += fmaxf(n0.w + m0.w, 0.f) + fmaxf(n1.w + m1.w, 0.f)
               + fmaxf(n2.w + m2.w, 0.f) + fmaxf(n3.w + m3.w, 0.f);
    }
    for (; i < end; i++) {
        int p0 = g_payload[i];
        float4 n0 = nf4[(long long)(p0 & 0x1FFFF) * 16 + q];
        int c0 = ((p0 >> 17) & 7) * 12 + ((p0 >> 20) & 7) * 2 + ((p0 >> 23) & 1);
        float4 m0 = combo[c0 * 16 + q];
        acc.x += fmaxf(n0.x + m0.x, 0.f);
        acc.y += fmaxf(n0.y + m0.y, 0.f);
        acc.z += fmaxf(n0.z + m0.z, 0.f);
        acc.w += fmaxf(n0.w + m0.w, 0.f);
    }
    ((float4*)g_hbuf)[(long long)gid * 16 + q] = acc;
}

// ---------------------------------------------------------------------------
// K3: h1 = h @ W1^T + b1 + BN partials. (R9 form: 2ch x half-K per thread)
// ---------------------------------------------------------------------------
__global__ void __launch_bounds__(128) k_gemm1(const float* __restrict__ W1,  // [128,64]
                                               const float* __restrict__ b1,
                                               int N)
{
    __shared__ float4 hsh[2][8 * 16];
    int tid = threadIdx.x;
    int p  = tid >> 1;
    int kh = tid & 1;
    int rowoff = tid >> 4;
    int kslot  = tid & 15;

    float4 w0[8], w1[8];
#pragma unroll
    for (int k4 = 0; k4 < 8; k4++) {
        w0[k4] = ((const float4*)W1)[(2 * p + 0) * 16 + kh * 8 + k4];
        w1[k4] = ((const float4*)W1)[(2 * p + 1) * 16 + kh * 8 + k4];
    }
    float bj = __ldg(b1 + tid);

    float lsum = 0.0f, lsq = 0.0f;

    long long step = (long long)GRID1 * 8;
    long long r0 = (long long)blockIdx.x * 8;

    float4 v = make_float4(0.f, 0.f, 0.f, 0.f);
    if (r0 + rowoff < N) v = ((const float4*)g_hbuf)[(r0 + rowoff) * 16 + kslot];

    int buf = 0;
    for (; r0 < N; r0 += step) {
        hsh[buf][tid] = v;
        __syncthreads();

        long long rn = r0 + step;
        if (rn + rowoff < N) v = ((const float4*)g_hbuf)[(rn + rowoff) * 16 + kslot];
        else                 v = make_float4(0.f, 0.f, 0.f, 0.f);

        float a0[8], a1[8];
#pragma unroll
        for (int r = 0; r < 8; r++) { a0[r] = 0.0f; a1[r] = 0.0f; }
#pragma unroll
        for (int k4 = 0; k4 < 8; k4++) {
            float4 wv0 = w0[k4];
            float4 wv1 = w1[k4];
#pragma unroll
            for (int r = 0; r < 8; r++) {
                float4 h = hsh[buf][r * 16 + kh * 8 + k4];
                a0[r] += wv0.x * h.x + wv0.y * h.y + wv0.z * h.z + wv0.w * h.w;
                a1[r] += wv1.x * h.x + wv1.y * h.y + wv1.z * h.z + wv1.w * h.w;
            }
        }

        long long base = r0 * 128 + tid;
#pragma unroll
        for (int r = 0; r < 8; r++) {
            float f0 = a0[r] + __shfl_xor_sync(0xffffffffu, a0[r], 1);
            float f1 = a1[r] + __shfl_xor_sync(0xffffffffu, a1[r], 1);
            float val = (kh ? f1 : f0) + bj;
            if (r0 + r < N) {
                g_h1[base + r * 128] = val;
                lsum += val; lsq += val * val;
            }
        }
        buf ^= 1;
    }
    g_psum[tid * GRID1 + blockIdx.x] = lsum;
    g_psq [tid * GRID1 + blockIdx.x] = lsq;
}

// ---------------------------------------------------------------------------
// K4: 128 blocks x 256 threads; coalesced BN reduction -> scale/shift.
// ---------------------------------------------------------------------------
__global__ void __launch_bounds__(256) k_bn(const float* __restrict__ gamma,
                                            const float* __restrict__ beta,
                                            double invN)
{
    __shared__ double ss[256], qq[256];
    int j = blockIdx.x;
    int t = threadIdx.x;

    double s = 0.0, q = 0.0;
    for (int b = t; b < GRID1; b += 256) {
        s += (double)g_psum[j * GRID1 + b];
        q += (double)g_psq [j * GRID1 + b];
    }
    ss[t] = s; qq[t] = q;
    __syncthreads();
    for (int off = 128; off > 0; off >>= 1) {
        if (t < off) { ss[t] += ss[t + off]; qq[t] += qq[t + off]; }
        __syncthreads();
    }
    if (t == 0) {
        float mean = (float)(ss[0] * invN);
        float var  = (float)(qq[0] * invN) - mean * mean;
        float inv  = rsqrtf(var + 1e-5f);
        float sc   = gamma[j] * inv;
        g_scale[j] = sc;
        g_shift[j] = beta[j] - mean * sc;
    }
}

// ---------------------------------------------------------------------------
// K5: out = relu(scale*h1 + shift) @ W2^T + b2. (R5-best form)
// ---------------------------------------------------------------------------
__global__ void __launch_bounds__(128) k_gemm2(const float* __restrict__ W2,  // [64,128]
                                               const float* __restrict__ b2,
                                               float* __restrict__ out,
                                               int N)
{
    __shared__ float4 ash[8 * 32];
    __shared__ float  sc[128], sh[128];
    __shared__ float  partial[8 * 64];
    int tid = threadIdx.x;
    int i  = tid & 63;
    int hh = tid >> 6;

    float4 w[16];
#pragma unroll
    for (int k4 = 0; k4 < 16; k4++)
        w[k4] = ((const float4*)W2)[i * 32 + hh * 16 + k4];
    sc[tid] = g_scale[tid];
    sh[tid] = g_shift[tid];
    float bi = __ldg(b2 + i);
    __syncthreads();

    long long step = (long long)GRID1 * 8;
    long long r0 = (long long)blockIdx.x * 8;

    float4 v[2];
#pragma unroll
    for (int t = 0; t < 2; t++) {
        int idx = tid + t * 128;
        long long row = r0 + (idx >> 5);
        v[t] = (row < N) ? ((const float4*)g_h1)[row * 32 + (idx & 31)]
                         : make_float4(0.f, 0.f, 0.f, 0.f);
    }

    for (; r0 < N; r0 += step) {
#pragma unroll
        for (int t = 0; t < 2; t++) {
            int idx = tid + t * 128;
            int j = (idx & 31) * 4;
            float4 a;
            a.x = fmaxf(fmaf(sc[j + 0], v[t].x, sh[j + 0]), 0.0f);
            a.y = fmaxf(fmaf(sc[j + 1], v[t].y, sh[j + 1]), 0.0f);
            a.z = fmaxf(fmaf(sc[j + 2], v[t].z, sh[j + 2]), 0.0f);
            a.w = fmaxf(fmaf(sc[j + 3], v[t].w, sh[j + 3]), 0.0f);
            ash[idx] = a;
        }
        __syncthreads();

        long long rn = r0 + step;
#pragma unroll
        for (int t = 0; t < 2; t++) {
            int idx = tid + t * 128;
            long long row = rn + (idx >> 5);
            v[t] = (row < N) ? ((const float4*)g_h1)[row * 32 + (idx & 31)]
                             : make_float4(0.f, 0.f, 0.f, 0.f);
        }

        float acc[8];
#pragma unroll
        for (int r = 0; r < 8; r++) acc[r] = 0.0f;
#pragma unroll
        for (int k4 = 0; k4 < 16; k4++) {
            float4 wv = w[k4];
#pragma unroll
            for (int r = 0; r < 8; r++) {
                float4 h = ash[r * 32 + hh * 16 + k4];
                acc[r] += wv.x * h.x + wv.y * h.y + wv.z * h.z + wv.w * h.w;
            }
        }

        if (hh == 1) {
#pragma unroll
            for (int r = 0; r < 8; r++) partial[r * 64 + i] = acc[r];
        }
        __syncthreads();
        if (hh == 0) {
#pragma unroll
            for (int r = 0; r < 8; r++) {
                if (r0 + r < N)
                    out[(r0 + r) * 64 + i] = acc[r] + partial[r * 64 + i] + bi;
            }
        }
    }
}

// ---------------------------------------------------------------------------
// Binding: size-driven anchor on the unique size-320 buffer (bond_emb0).
// ---------------------------------------------------------------------------
extern "C" void kernel_launch(void* const* d_in, const int* in_sizes, int n_in,
                              void* d_out, int out_size)
{
    const float* nf = (const float*)d_in[0];
    const void*  ef = d_in[1];
    const void*  ei = d_in[2];

    int iEmb0 = -1;
    for (int i = 3; i < n_in; i++) {
        if (in_sizes[i] == 320) { iEmb0 = i; break; }
    }
    if (iEmb0 < 0) iEmb0 = 6;

    const float* eps   = (const float*)d_in[iEmb0 - 1];
    const float* e0    = (const float*)d_in[iEmb0];
    const float* e1    = (const float*)d_in[iEmb0 + 1];
    const float* e2    = (const float*)d_in[iEmb0 + 2];
    const float* W1    = (const float*)d_in[iEmb0 + 3];
    const float* b1    = (const float*)d_in[iEmb0 + 4];
    const float* gamma = (const float*)d_in[iEmb0 + 5];
    const float* beta  = (const float*)d_in[iEmb0 + 6];
    const float* W2    = (const float*)d_in[iEmb0 + 7];
    const float* b2    = (const float*)d_in[iEmb0 + 8];

    int N = in_sizes[0] / 64;
    long long E = (long long)in_sizes[1] / 3;

    k_probe<<<1, 1>>>((const long long*)ef);

    // CSR build
    int nscan = (N + 1023) / 1024;
    k_zero<<<(N + 255) / 256, 256>>>(N);
    k_hist<<<(int)((E + 255) / 256), 256>>>(ei, E, N);
    k_scanA<<<nscan, 1024>>>(N);
    k_scanB<<<1, 128>>>(nscan);
    k_scanC<<<(N + 255) / 256, 256>>>(N, (int)E);
    k_fill<<<(int)((E + 255) / 256), 256>>>(ef, ei, E, N);

    // gather-reduce (also applies (1+eps)*x)
    k_gather<<<(N + 15) / 16, 256>>>((const float4*)nf,
                                     (const float4*)e0, (const float4*)e1, (const float4*)e2,
                                     eps, N);

    k_gemm1<<<GRID1, 128>>>(W1, b1, N);
    k_bn<<<128, 256>>>(gamma, beta, 1.0 / (double)N);
    k_gemm2<<<GRID1, 128>>>(W2, b2, (float*)d_out, N);
}